// round 16
// baseline (speedup 1.0000x reference)
#include <cuda_runtime.h>
#include <cuda_bf16.h>
#include <cstdint>
#include <math.h>

#define B 1024
#define S 50000
#define SPAD 50048
#define D 128
#define H 8
#define NROWS (B*H)          // 8192 rows (user,head)
#define KSPLIT 23
#define NT64 782             // SPAD/64 tiles (= 23 * 34 exactly)
#define TPT 34               // tiles per split
#define RPITCH 256           // smem row pitch bytes, XOR-swizzled chunks (16B units)

// ---------------- device scratch ----------------
__device__ __nv_bfloat16 g_Qb[NROWS * D];        // Q rows bf16, pre-scaled by log2e/sqrt(D)
__device__ __nv_bfloat16 g_Mb[SPAD * D];         // source emb bf16 (pad rows zero)
__device__ float g_Num[NROWS * D];               // raw numerators (RED-accumulated, 4 MB)
__device__ float g_Den[NROWS];                   // denominators (RED-accumulated)

// ---------------- helpers ----------------
__device__ __forceinline__ uint32_t smem_u32(const void* p) {
    uint32_t a; asm("{ .reg .u64 t; cvta.to.shared.u64 t, %1; cvt.u32.u64 %0, t; }" : "=r"(a) : "l"(p));
    return a;
}
__device__ __forceinline__ void cp16(uint32_t dst, const void* src) {
    asm volatile("cp.async.cg.shared.global [%0], [%1], 16;" :: "r"(dst), "l"(src));
}
#define CP_COMMIT() asm volatile("cp.async.commit_group;")
#define CP_WAIT0()  asm volatile("cp.async.wait_group 0;")

__device__ __forceinline__ void ldsm4(uint32_t& r0, uint32_t& r1, uint32_t& r2, uint32_t& r3, uint32_t a) {
    asm volatile("ldmatrix.sync.aligned.m8n8.x4.shared.b16 {%0,%1,%2,%3}, [%4];"
                 : "=r"(r0), "=r"(r1), "=r"(r2), "=r"(r3) : "r"(a));
}
__device__ __forceinline__ void ldsm4t(uint32_t& r0, uint32_t& r1, uint32_t& r2, uint32_t& r3, uint32_t a) {
    asm volatile("ldmatrix.sync.aligned.m8n8.x4.trans.shared.b16 {%0,%1,%2,%3}, [%4];"
                 : "=r"(r0), "=r"(r1), "=r"(r2), "=r"(r3) : "r"(a));
}
__device__ __forceinline__ void mma16816(float* c, uint32_t a0, uint32_t a1, uint32_t a2, uint32_t a3,
                                         uint32_t b0, uint32_t b1) {
    asm volatile("mma.sync.aligned.m16n8k16.row.col.f32.bf16.bf16.f32 "
                 "{%0,%1,%2,%3},{%4,%5,%6,%7},{%8,%9},{%0,%1,%2,%3};"
                 : "+f"(c[0]), "+f"(c[1]), "+f"(c[2]), "+f"(c[3])
                 : "r"(a0), "r"(a1), "r"(a2), "r"(a3), "r"(b0), "r"(b1));
}
// 2^x via MUFU.EX2 (single SASS instruction)
__device__ __forceinline__ float ex2(float x) {
    float r;
    asm("ex2.approx.ftz.f32 %0, %1;" : "=f"(r) : "f"(x));
    return r;
}
__device__ __forceinline__ uint32_t packbf2(float lo, float hi) {
    __nv_bfloat162 v = __floats2bfloat162_rn(lo, hi);
    return *(uint32_t*)&v;
}
// swizzled byte offset within a 256B-pitch tile: chunk index XOR (row & 7)
__device__ __forceinline__ uint32_t swzoff(int row, int ch) {
    return (uint32_t)(row * RPITCH + (((uint32_t)ch ^ ((uint32_t)row & 7u)) << 4));
}

// ---------------- Kernel 1: fused prep (qproj + zero accumulators + convert) ----------------
#define NQPROJ 512
#define NZNUM 1024
#define NZDEN 8
#define NCONV (SPAD * 32 / 256)     // 6256

__global__ __launch_bounds__(256)
void prep_kernel(const int* __restrict__ uid,
                 const float* __restrict__ user_emb,
                 const float* __restrict__ Wcm,
                 const float* __restrict__ src) {
    int tid = threadIdx.x;
    int bid = blockIdx.x;
    if (bid < NQPROJ) {
        // ---- qproj part ----
        __shared__ float sX[8 * 132];
        __shared__ int sU[8];
        int bx = bid >> 2;                   // 0..127
        int by = bid & 3;                    // 0..3
        int bu = bx * 8;
        if (tid < 8) sU[tid] = uid[bu + tid];
        __syncthreads();
        for (int i = tid; i < 8 * 128; i += 256) {
            int u = i >> 7, d = i & 127;
            sX[u * 132 + d] = user_emb[(size_t)sU[u] * D + d];
        }
        __syncthreads();
        const float scale = 1.4426950408889634f * rsqrtf(128.f);
        int o = by * 256 + tid;              // one output (h,e) per thread
        int h = o >> 7, e = o & 127;
        const float* w = Wcm + h * D * D + e;
        float acc[8];
#pragma unroll
        for (int u = 0; u < 8; u++) acc[u] = 0.f;
#pragma unroll 4
        for (int d = 0; d < D; d++) {
            float wv = w[d * D];
#pragma unroll
            for (int u = 0; u < 8; u++) acc[u] += sX[u * 132 + d] * wv;
        }
#pragma unroll
        for (int u = 0; u < 8; u++)
            g_Qb[((size_t)(bu + u) * H + h) * D + e] = __float2bfloat16(acc[u] * scale);
        return;
    }
    bid -= NQPROJ;
    if (bid < NZNUM) {      // zero g_Num
        size_t ii = (size_t)bid * 256 + tid;
        *(float4*)&g_Num[ii * 4] = make_float4(0.f, 0.f, 0.f, 0.f);
        return;
    }
    bid -= NZNUM;
    if (bid < NZDEN) {      // zero g_Den
        *(float4*)&g_Den[bid * 1024 + tid * 4] = make_float4(0.f, 0.f, 0.f, 0.f);
        return;
    }
    bid -= NZDEN;
    // ---- convert part ----
    long long i = (long long)bid * 256 + tid;   // one float4 per thread
    int s = (int)(i >> 5);
    int c = (int)(i & 31) << 2;
    float4 v = make_float4(0.f, 0.f, 0.f, 0.f);
    if (s < S) v = *(const float4*)&src[(size_t)s * D + c];
    *(__nv_bfloat162*)&g_Mb[(size_t)s * D + c]     = __floats2bfloat162_rn(v.x, v.y);
    *(__nv_bfloat162*)&g_Mb[(size_t)s * D + c + 2] = __floats2bfloat162_rn(v.z, v.w);
}

// ---------------- attention tile body: 32 rows x 64 src x 128 d per warp ----------------
// Addresses use XOR-swizzled 256B-pitch tiles: addr = base + ((k*32) ^ xs),
// xs = per-thread constant (chunk-half bit XOR (lane&7)<<4).
template<bool TAIL>
__device__ __forceinline__ void tile_body(uint32_t sqA0, uint32_t srcb_b, uint32_t srcb_v,
                                          uint32_t qxs, uint32_t bxs, uint32_t vxs,
                                          const float* aP00, const float* aP01,
                                          const float* aP10, const float* aP11,
                                          int s0c, float (&oacc)[2][16][4],
                                          float (&esum)[2][2]) {
    // ---- GEMM1: P[32 x 64] = Q[32 x 128] . Mtile^T  (B frags shared by both M-halves) ----
    float pa[2][8][4];
#pragma unroll
    for (int mh = 0; mh < 2; mh++)
#pragma unroll
        for (int n = 0; n < 8; n++)
#pragma unroll
            for (int q = 0; q < 4; q++) pa[mh][n][q] = 0.f;
#pragma unroll
    for (int k = 0; k < 8; k++) {
        uint32_t q00, q01, q02, q03, q10, q11, q12, q13;
        uint32_t qo = ((uint32_t)(k * 32)) ^ qxs;
        ldsm4(q00, q01, q02, q03, sqA0 + qo);
        ldsm4(q10, q11, q12, q13, sqA0 + 4096 + qo);
        uint32_t bo = ((uint32_t)(k * 32)) ^ bxs;
#pragma unroll
        for (int j = 0; j < 4; j++) {
            uint32_t b0, b1, b2, b3;
            ldsm4(b0, b1, b2, b3, srcb_b + j * 4096 + bo);
            mma16816(pa[0][2 * j],     q00, q01, q02, q03, b0, b1);
            mma16816(pa[0][2 * j + 1], q00, q01, q02, q03, b2, b3);
            mma16816(pa[1][2 * j],     q10, q11, q12, q13, b0, b1);
            mma16816(pa[1][2 * j + 1], q10, q11, q12, q13, b2, b3);
        }
    }
    // ---- epilogue: e = 2^(relu(p*a)) ----
    uint32_t er[2][4][4];
#pragma unroll
    for (int mh = 0; mh < 2; mh++) {
        const float* ap0 = mh ? aP10 : aP00;
        const float* ap1 = mh ? aP11 : aP01;
#pragma unroll
        for (int n = 0; n < 8; n++) {
            float2 a0 = *(const float2*)(ap0 + 8 * n);
            float2 a1 = *(const float2*)(ap1 + 8 * n);
            float e00 = ex2(fmaxf(pa[mh][n][0] * a0.x, 0.f));
            float e01 = ex2(fmaxf(pa[mh][n][1] * a0.y, 0.f));
            float e10 = ex2(fmaxf(pa[mh][n][2] * a1.x, 0.f));
            float e11 = ex2(fmaxf(pa[mh][n][3] * a1.y, 0.f));
            if (TAIL) {
                bool v0 = (s0c + 8 * n) < S;
                bool v1 = (s0c + 8 * n + 1) < S;
                e00 = v0 ? e00 : 0.f;  e01 = v1 ? e01 : 0.f;
                e10 = v0 ? e10 : 0.f;  e11 = v1 ? e11 : 0.f;
            }
            esum[mh][0] += e00 + e01;
            esum[mh][1] += e10 + e11;
            er[mh][n >> 1][(n & 1) * 2 + 0] = packbf2(e00, e01);
            er[mh][n >> 1][(n & 1) * 2 + 1] = packbf2(e10, e11);
        }
    }
    // ---- GEMM2: O[32 x 128] += E[32 x 64] . Mtile  (V frags shared by both M-halves) ----
#pragma unroll
    for (int kk = 0; kk < 4; kk++) {
#pragma unroll
        for (int j = 0; j < 8; j++) {
            uint32_t v0, v1, v2, v3;
            ldsm4t(v0, v1, v2, v3, srcb_v + kk * 4096 + (((uint32_t)(j * 32)) ^ vxs));
            mma16816(oacc[0][2 * j],     er[0][kk][0], er[0][kk][1], er[0][kk][2], er[0][kk][3], v0, v1);
            mma16816(oacc[0][2 * j + 1], er[0][kk][0], er[0][kk][1], er[0][kk][2], er[0][kk][3], v2, v3);
            mma16816(oacc[1][2 * j],     er[1][kk][0], er[1][kk][1], er[1][kk][2], er[1][kk][3], v0, v1);
            mma16816(oacc[1][2 * j + 1], er[1][kk][0], er[1][kk][1], er[1][kk][2], er[1][kk][3], v2, v3);
        }
    }
}

// ---------------- Kernel 2: fused attention (mma.sync bf16, 2-stage, 3 CTAs/SM) ----------------
// grid (KSPLIT, 64); 128 threads. CTA = 128 rows (16 users); warp = 32 rows (4 users).
#define SQ_OFF   0u                                       // 128 x 256 = 32768
#define SRC_OFF(st)  (32768u + (uint32_t)(st) * 16384u)   // 2 buffers, 64 x 256 each
#define SA_OFF(st)   (65536u + (uint32_t)(st) * 4096u)    // 2 buffers, 16 users x 256B
#define SUID_OFF 73728u
#define SMEM_BYTES 73792u

__global__ __launch_bounds__(128, 3)
void attn_kernel(const int* __restrict__ uid, const float* __restrict__ A_us) {
    extern __shared__ char sm[];
    const uint32_t sb = smem_u32(sm);
    const int tid = threadIdx.x;
    const int lane = tid & 31;
    const int w = tid >> 5;
    const int ks = blockIdx.x;
    const int rb = blockIdx.y;
    const int rowbase = rb * 128;       // 128 global rows per CTA
    int* sUid = (int*)(sm + SUID_OFF);

    if (tid < 16) sUid[tid] = uid[rb * 16 + tid];
    __syncthreads();

    // stage Q slab [128 rows][128] bf16 into swizzled 256B-pitch smem
#pragma unroll
    for (int j = 0; j < 16; j++) {
        int idx = tid + j * 128;
        int row = idx >> 4, ch = idx & 15;
        uint4 v = *(const uint4*)&g_Qb[(size_t)(rowbase + row) * D + ch * 8];
        *(uint4*)(sm + SQ_OFF + swzoff(row, ch)) = v;
    }

    const int t0 = ks * TPT;
    const int t1 = t0 + TPT;

    // prologue: prefetch tile t0 -> buf0
    {
        int s0 = t0 * 64;
        uint32_t srcd = sb + SRC_OFF(0);
        uint32_t sad  = sb + SA_OFF(0);
#pragma unroll
        for (int j = 0; j < 8; j++) {
            int idx = tid + j * 128;
            int row = idx >> 4, ch = idx & 15;
            cp16(srcd + swzoff(row, ch), &g_Mb[(size_t)(s0 + row) * D + ch * 8]);
        }
#pragma unroll
        for (int j = 0; j < 2; j++) {
            int idx = tid + j * 128;
            int u = idx >> 4, cc = (idx & 15) * 4;
            if (s0 + cc + 4 <= S)
                cp16(sad + u * 256 + (idx & 15) * 16, &A_us[(size_t)sUid[u] * S + s0 + cc]);
        }
        CP_COMMIT();
    }

    // per-thread swizzle constants and base addresses
    const uint32_t sxorB = (uint32_t)(lane & 7) << 4;
    const uint32_t qxs = (((uint32_t)(lane >> 4)) << 4) ^ sxorB;        // Q chunk-half ^ row-xor
    const uint32_t bxs = (((uint32_t)((lane >> 3) & 1)) << 4) ^ sxorB;  // B chunk-half ^ row-xor
    const uint32_t vxs = qxs;                                           // V: same half bit as Q
    const uint32_t sqA0 = sb + SQ_OFF + (uint32_t)(32 * w + (lane & 15)) * RPITCH;
    const uint32_t rb1o = (uint32_t)(((lane >> 4) & 1) * 8 + (lane & 7)) * RPITCH;
    const uint32_t rb2o = (uint32_t)(((lane >> 3) & 1) * 8 + (lane & 7)) * RPITCH;
    const int cb = 2 * (lane & 3);

    float oacc[2][16][4];
#pragma unroll
    for (int mh = 0; mh < 2; mh++)
#pragma unroll
        for (int n = 0; n < 16; n++)
#pragma unroll
            for (int q = 0; q < 4; q++) oacc[mh][n][q] = 0.f;
    float esum[2][2];
    esum[0][0] = esum[0][1] = esum[1][0] = esum[1][1] = 0.f;

    for (int t = t0; t < t1; ++t) {
        int bufi = (t - t0) & 1;
        CP_WAIT0();
        __syncthreads();
        if (t + 1 < t1) {   // prefetch t+1 into the other buffer (consumed at t-1)
            int s0n = (t + 1) * 64;
            uint32_t srcn = sb + SRC_OFF(bufi ^ 1);
            uint32_t san  = sb + SA_OFF(bufi ^ 1);
#pragma unroll
            for (int j = 0; j < 8; j++) {
                int idx = tid + j * 128;
                int row = idx >> 4, ch = idx & 15;
                cp16(srcn + swzoff(row, ch), &g_Mb[(size_t)(s0n + row) * D + ch * 8]);
            }
#pragma unroll
            for (int j = 0; j < 2; j++) {
                int idx = tid + j * 128;
                int u = idx >> 4, cc = (idx & 15) * 4;
                if (s0n + cc + 4 <= S)
                    cp16(san + u * 256 + (idx & 15) * 16, &A_us[(size_t)sUid[u] * S + s0n + cc]);
            }
            CP_COMMIT();
        }
        uint32_t srcb = sb + SRC_OFF(bufi);
        const float* sAa = (const float*)(sm + SA_OFF(bufi));
        // warp w owns users 4w..4w+3: mh0 -> users 4w,4w+1 ; mh1 -> users 4w+2,4w+3
        const float* aP00 = sAa + (4 * w + 0) * 64 + cb;
        const float* aP01 = sAa + (4 * w + 1) * 64 + cb;
        const float* aP10 = sAa + (4 * w + 2) * 64 + cb;
        const float* aP11 = sAa + (4 * w + 3) * 64 + cb;
        int s0 = t * 64;
        if (t == NT64 - 1)
            tile_body<true >(sqA0, srcb + rb1o, srcb + rb2o, qxs, bxs, vxs,
                             aP00, aP01, aP10, aP11, s0 + cb, oacc, esum);
        else
            tile_body<false>(sqA0, srcb + rb1o, srcb + rb2o, qxs, bxs, vxs,
                             aP00, aP01, aP10, aP11, s0 + cb, oacc, esum);
    }

    // ---- denominators: reduce over the 4 lanes sharing each row, RED into g_Den ----
#pragma unroll
    for (int mh = 0; mh < 2; mh++)
#pragma unroll
        for (int hh = 0; hh < 2; hh++) {
            esum[mh][hh] += __shfl_xor_sync(0xffffffffu, esum[mh][hh], 1);
            esum[mh][hh] += __shfl_xor_sync(0xffffffffu, esum[mh][hh], 2);
        }
    int r0 = rowbase + 32 * w + (lane >> 2);
    if ((lane & 3) == 0) {
        atomicAdd(&g_Den[r0],      esum[0][0]);
        atomicAdd(&g_Den[r0 + 8],  esum[0][1]);
        atomicAdd(&g_Den[r0 + 16], esum[1][0]);
        atomicAdd(&g_Den[r0 + 24], esum[1][1]);
    }
    // ---- raw numerators: RED (fire-and-forget) into g_Num ----
#pragma unroll
    for (int mh = 0; mh < 2; mh++) {
        int rr = r0 + 16 * mh;
#pragma unroll
        for (int nf = 0; nf < 16; nf++) {
            int c = 8 * nf + cb;
            float* d0 = &g_Num[(size_t)rr * D + c];
            float* d1 = &g_Num[(size_t)(rr + 8) * D + c];
            atomicAdd(d0,     oacc[mh][nf][0]);
            atomicAdd(d0 + 1, oacc[mh][nf][1]);
            atomicAdd(d1,     oacc[mh][nf][2]);
            atomicAdd(d1 + 1, oacc[mh][nf][3]);
        }
    }
}

// ---------------- Kernel 3: normalize + W1 GEMM (8-way split-K, 1024 thr) + elu + Xu ----------------
__global__ __launch_bounds__(1024)
void out_kernel(const int* __restrict__ uid,
                const float* __restrict__ user_emb,
                const float* __restrict__ W1,
                float* __restrict__ out) {
    extern __shared__ float dynsm[];
    float* smc  = dynsm;            // [8 users][1024]
    float* sred = dynsm + 8 * 1024; // [8 grp][8 users * 128 cols]
    float* sden = sred + 8 * 1024;  // [64] reciprocal denominators
    int bu = blockIdx.x * 8;
    int tid = threadIdx.x;
    if (tid < 64) sden[tid] = 1.f / g_Den[bu * 8 + tid];
    __syncthreads();
    // load + normalize m_hat for 8 users (2048 float4, 1024 threads -> 2 each)
#pragma unroll
    for (int jj = 0; jj < 2; jj++) {
        int ii = tid + jj * 1024;
        float4 v = *(const float4*)&g_Num[(size_t)bu * 1024 + (size_t)ii * 4];
        float inv = sden[ii >> 5];      // row = (ii*4)/128
        v.x *= inv; v.y *= inv; v.z *= inv; v.w *= inv;
        *(float4*)&smc[ii * 4] = v;
    }
    __syncthreads();
    int col = tid & 127;
    int grp = tid >> 7;          // 0..7, covers k in [grp*128, grp*128+128)
    int ibase = grp * 128;
    float acc[8];
#pragma unroll
    for (int uu = 0; uu < 8; uu++) acc[uu] = 0.f;
#pragma unroll 4
    for (int i = 0; i < 128; i++) {
        float wv = W1[(ibase + i) * D + col];     // coalesced across lanes
#pragma unroll
        for (int uu = 0; uu < 8; uu++) acc[uu] += smc[uu * 1024 + ibase + i] * wv;
    }
#pragma unroll
    for (int uu = 0; uu < 8; uu++) sred[grp * 1024 + uu * 128 + col] = acc[uu];
    __syncthreads();
    // one thread per (user, col): combine 8 groups, elu, residual
    int uu = tid >> 7;           // reuse grp slot as user index
    float v = 0.f;
#pragma unroll
    for (int g = 0; g < 8; g++) v += sred[g * 1024 + uu * 128 + col];
    float e = v > 0.f ? v : expm1f(v);
    out[(size_t)(bu + uu) * D + col] = e + user_emb[(size_t)uid[bu + uu] * D + col];
}

// ---------------------------------------------------------------------------
extern "C" void kernel_launch(void* const* d_in, const int* in_sizes, int n_in,
                              void* d_out, int out_size) {
    const int*   X_user_id = (const int*)d_in[0];
    const float* user_emb  = (const float*)d_in[1];
    const float* src       = (const float*)d_in[2];
    const float* Wcm       = (const float*)d_in[3];
    const float* W1        = (const float*)d_in[4];
    const float* A_us      = (const float*)d_in[5];
    float* out = (float*)d_out;

    cudaFuncSetAttribute(attn_kernel, cudaFuncAttributeMaxDynamicSharedMemorySize, SMEM_BYTES);
    cudaFuncSetAttribute(out_kernel, cudaFuncAttributeMaxDynamicSharedMemorySize, 65792);

    prep_kernel<<<NQPROJ + NZNUM + NZDEN + NCONV, 256>>>(X_user_id, user_emb, Wcm, src);
    attn_kernel<<<dim3(KSPLIT, NROWS / 128), 128, SMEM_BYTES>>>(X_user_id, A_us);
    out_kernel<<<B / 8, 1024, 65792>>>(X_user_id, user_emb, W1, out);
}

// round 17
// speedup vs baseline: 2.1634x; 2.1634x over previous
#include <cuda_runtime.h>
#include <cuda_bf16.h>
#include <cstdint>
#include <math.h>

#define B 1024
#define S 50000
#define SPAD 50048
#define D 128
#define H 8
#define NROWS (B*H)          // 8192 rows (user,head)
#define KSPLIT 23
#define NT64 782             // SPAD/64 tiles (= 23 * 34 exactly)
#define TPT 34               // tiles per split
#define PITCH 272            // smem row pitch bytes (136 bf16) — conflict-free ldmatrix

// ---------------- device scratch ----------------
__device__ __nv_bfloat16 g_Qb[NROWS * D];        // Q rows bf16, pre-scaled by log2e/sqrt(D)
__device__ __nv_bfloat16 g_Mb[SPAD * D];         // source emb bf16 (pad rows zero)
__device__ float g_Num[NROWS * D];               // raw numerators (RED-accumulated, 4 MB)
__device__ float g_Den[NROWS];                   // denominators (RED-accumulated)

// ---------------- helpers ----------------
__device__ __forceinline__ uint32_t smem_u32(const void* p) {
    uint32_t a; asm("{ .reg .u64 t; cvta.to.shared.u64 t, %1; cvt.u32.u64 %0, t; }" : "=r"(a) : "l"(p));
    return a;
}
__device__ __forceinline__ void cp16(uint32_t dst, const void* src) {
    asm volatile("cp.async.cg.shared.global [%0], [%1], 16;" :: "r"(dst), "l"(src));
}
#define CP_COMMIT() asm volatile("cp.async.commit_group;")
#define CP_WAIT0()  asm volatile("cp.async.wait_group 0;")
#define CP_WAIT1()  asm volatile("cp.async.wait_group 1;")

__device__ __forceinline__ void ldsm4(uint32_t& r0, uint32_t& r1, uint32_t& r2, uint32_t& r3, uint32_t a) {
    asm volatile("ldmatrix.sync.aligned.m8n8.x4.shared.b16 {%0,%1,%2,%3}, [%4];"
                 : "=r"(r0), "=r"(r1), "=r"(r2), "=r"(r3) : "r"(a));
}
__device__ __forceinline__ void ldsm4t(uint32_t& r0, uint32_t& r1, uint32_t& r2, uint32_t& r3, uint32_t a) {
    asm volatile("ldmatrix.sync.aligned.m8n8.x4.trans.shared.b16 {%0,%1,%2,%3}, [%4];"
                 : "=r"(r0), "=r"(r1), "=r"(r2), "=r"(r3) : "r"(a));
}
__device__ __forceinline__ void mma16816(float* c, uint32_t a0, uint32_t a1, uint32_t a2, uint32_t a3,
                                         uint32_t b0, uint32_t b1) {
    asm volatile("mma.sync.aligned.m16n8k16.row.col.f32.bf16.bf16.f32 "
                 "{%0,%1,%2,%3},{%4,%5,%6,%7},{%8,%9},{%0,%1,%2,%3};"
                 : "+f"(c[0]), "+f"(c[1]), "+f"(c[2]), "+f"(c[3])
                 : "r"(a0), "r"(a1), "r"(a2), "r"(a3), "r"(b0), "r"(b1));
}
// 2^x via MUFU.EX2 (single SASS instruction)
__device__ __forceinline__ float ex2(float x) {
    float r;
    asm("ex2.approx.ftz.f32 %0, %1;" : "=f"(r) : "f"(x));
    return r;
}
__device__ __forceinline__ uint32_t packbf2(float lo, float hi) {
    __nv_bfloat162 v = __floats2bfloat162_rn(lo, hi);
    return *(uint32_t*)&v;
}

// ---------------- Kernel 1: fused prep (qproj + zero accumulators + convert) ----------------
// Block order puts the longest-critical-path work (qproj) in wave 1:
// blocks [0, 512)            : Q projection -> bf16, pre-scaled by log2e/sqrt(D)
// blocks [512, 512+1024)     : zero g_Num
// blocks [.., +8)            : zero g_Den
// blocks [.., +NCONV)        : source emb fp32 -> bf16
#define NQPROJ 512
#define NZNUM 1024
#define NZDEN 8
#define NCONV (SPAD * 32 / 256)     // 6256

__global__ __launch_bounds__(256)
void prep_kernel(const int* __restrict__ uid,
                 const float* __restrict__ user_emb,
                 const float* __restrict__ Wcm,
                 const float* __restrict__ src) {
    int tid = threadIdx.x;
    int bid = blockIdx.x;
    if (bid < NQPROJ) {
        // ---- qproj part ----
        __shared__ float sX[8 * 132];
        __shared__ int sU[8];
        int bx = bid >> 2;                   // 0..127
        int by = bid & 3;                    // 0..3
        int bu = bx * 8;
        if (tid < 8) sU[tid] = uid[bu + tid];
        __syncthreads();
        for (int i = tid; i < 8 * 128; i += 256) {
            int u = i >> 7, d = i & 127;
            sX[u * 132 + d] = user_emb[(size_t)sU[u] * D + d];
        }
        __syncthreads();
        const float scale = 1.4426950408889634f * rsqrtf(128.f);
        int o = by * 256 + tid;              // one output (h,e) per thread
        int h = o >> 7, e = o & 127;
        const float* w = Wcm + h * D * D + e;
        float acc[8];
#pragma unroll
        for (int u = 0; u < 8; u++) acc[u] = 0.f;
#pragma unroll 4
        for (int d = 0; d < D; d++) {
            float wv = w[d * D];
#pragma unroll
            for (int u = 0; u < 8; u++) acc[u] += sX[u * 132 + d] * wv;
        }
#pragma unroll
        for (int u = 0; u < 8; u++)
            g_Qb[((size_t)(bu + u) * H + h) * D + e] = __float2bfloat16(acc[u] * scale);
        return;
    }
    bid -= NQPROJ;
    if (bid < NZNUM) {      // zero g_Num
        size_t ii = (size_t)bid * 256 + tid;
        *(float4*)&g_Num[ii * 4] = make_float4(0.f, 0.f, 0.f, 0.f);
        return;
    }
    bid -= NZNUM;
    if (bid < NZDEN) {      // zero g_Den
        *(float4*)&g_Den[bid * 1024 + tid * 4] = make_float4(0.f, 0.f, 0.f, 0.f);
        return;
    }
    bid -= NZDEN;
    // ---- convert part ----
    long long i = (long long)bid * 256 + tid;   // one float4 per thread
    int s = (int)(i >> 5);
    int c = (int)(i & 31) << 2;
    float4 v = make_float4(0.f, 0.f, 0.f, 0.f);
    if (s < S) v = *(const float4*)&src[(size_t)s * D + c];
    *(__nv_bfloat162*)&g_Mb[(size_t)s * D + c]     = __floats2bfloat162_rn(v.x, v.y);
    *(__nv_bfloat162*)&g_Mb[(size_t)s * D + c + 2] = __floats2bfloat162_rn(v.z, v.w);
}

// ---------------- attention tile body: 32 rows x 64 src x 128 d per warp ----------------
template<bool TAIL>
__device__ __forceinline__ void tile_body(uint32_t sqA0, uint32_t srcb,
                                          const float* aP00, const float* aP01,
                                          const float* aP10, const float* aP11,
                                          int s0c, float (&oacc)[2][16][4],
                                          float (&esum)[2][2],
                                          uint32_t b1o, uint32_t vo) {
    // ---- GEMM1: P[32 x 64] = Q[32 x 128] . Mtile^T  (B frags shared by both M-halves) ----
    float pa[2][8][4];
#pragma unroll
    for (int mh = 0; mh < 2; mh++)
#pragma unroll
        for (int n = 0; n < 8; n++)
#pragma unroll
            for (int q = 0; q < 4; q++) pa[mh][n][q] = 0.f;
#pragma unroll
    for (int k = 0; k < 8; k++) {
        uint32_t q00, q01, q02, q03, q10, q11, q12, q13;
        ldsm4(q00, q01, q02, q03, sqA0 + k * 32);
        ldsm4(q10, q11, q12, q13, sqA0 + 16 * PITCH + k * 32);
#pragma unroll
        for (int j = 0; j < 4; j++) {
            uint32_t b0, b1, b2, b3;
            ldsm4(b0, b1, b2, b3, srcb + b1o + j * (16 * PITCH) + k * 32);
            mma16816(pa[0][2 * j],     q00, q01, q02, q03, b0, b1);
            mma16816(pa[0][2 * j + 1], q00, q01, q02, q03, b2, b3);
            mma16816(pa[1][2 * j],     q10, q11, q12, q13, b0, b1);
            mma16816(pa[1][2 * j + 1], q10, q11, q12, q13, b2, b3);
        }
    }
    // ---- epilogue: e = 2^(relu(p*a)) ----
    uint32_t er[2][4][4];
#pragma unroll
    for (int mh = 0; mh < 2; mh++) {
        const float* ap0 = mh ? aP10 : aP00;
        const float* ap1 = mh ? aP11 : aP01;
#pragma unroll
        for (int n = 0; n < 8; n++) {
            float2 a0 = *(const float2*)(ap0 + 8 * n);
            float2 a1 = *(const float2*)(ap1 + 8 * n);
            float e00 = ex2(fmaxf(pa[mh][n][0] * a0.x, 0.f));
            float e01 = ex2(fmaxf(pa[mh][n][1] * a0.y, 0.f));
            float e10 = ex2(fmaxf(pa[mh][n][2] * a1.x, 0.f));
            float e11 = ex2(fmaxf(pa[mh][n][3] * a1.y, 0.f));
            if (TAIL) {
                bool v0 = (s0c + 8 * n) < S;
                bool v1 = (s0c + 8 * n + 1) < S;
                e00 = v0 ? e00 : 0.f;  e01 = v1 ? e01 : 0.f;
                e10 = v0 ? e10 : 0.f;  e11 = v1 ? e11 : 0.f;
            }
            esum[mh][0] += e00 + e01;
            esum[mh][1] += e10 + e11;
            er[mh][n >> 1][(n & 1) * 2 + 0] = packbf2(e00, e01);
            er[mh][n >> 1][(n & 1) * 2 + 1] = packbf2(e10, e11);
        }
    }
    // ---- GEMM2: O[32 x 128] += E[32 x 64] . Mtile  (V frags shared by both M-halves) ----
#pragma unroll
    for (int kk = 0; kk < 4; kk++) {
#pragma unroll
        for (int j = 0; j < 8; j++) {
            uint32_t v0, v1, v2, v3;
            ldsm4t(v0, v1, v2, v3, srcb + vo + kk * (16 * PITCH) + j * 32);
            mma16816(oacc[0][2 * j],     er[0][kk][0], er[0][kk][1], er[0][kk][2], er[0][kk][3], v0, v1);
            mma16816(oacc[0][2 * j + 1], er[0][kk][0], er[0][kk][1], er[0][kk][2], er[0][kk][3], v2, v3);
            mma16816(oacc[1][2 * j],     er[1][kk][0], er[1][kk][1], er[1][kk][2], er[1][kk][3], v0, v1);
            mma16816(oacc[1][2 * j + 1], er[1][kk][0], er[1][kk][1], er[1][kk][2], er[1][kk][3], v2, v3);
        }
    }
}

// ---------------- Kernel 2: fused attention (mma.sync bf16, 3-stage cp.async) ----------------
// grid (KSPLIT, 64); 128 threads. CTA = 128 rows (16 users); warp = 32 rows (4 users).
#define SQ_OFF   0u
#define SRC_OFF(st)  (34816u + (uint32_t)(st) * 17408u)   // 3 buffers
#define SA_OFF(st)   (87040u + (uint32_t)(st) * 4352u)    // 3 buffers (16 users x 272B)
#define SUID_OFF 100096u
#define SMEM_BYTES 100224u

__global__ __launch_bounds__(128, 2)
void attn_kernel(const int* __restrict__ uid, const float* __restrict__ A_us) {
    extern __shared__ char sm[];
    const uint32_t sb = smem_u32(sm);
    const int tid = threadIdx.x;
    const int lane = tid & 31;
    const int w = tid >> 5;
    const int ks = blockIdx.x;
    const int rb = blockIdx.y;
    const int rowbase = rb * 128;       // 128 global rows per CTA
    int* sUid = (int*)(sm + SUID_OFF);

    if (tid < 16) sUid[tid] = uid[rb * 16 + tid];
    __syncthreads();

    // stage Q slab [128 rows][128] bf16 into pitch-272 smem
#pragma unroll
    for (int j = 0; j < 16; j++) {
        int idx = tid + j * 128;
        int row = idx >> 4, ch = idx & 15;
        uint4 v = *(const uint4*)&g_Qb[(size_t)(rowbase + row) * D + ch * 8];
        *(uint4*)(sm + SQ_OFF + row * PITCH + ch * 16) = v;
    }

    const int t0 = ks * TPT;
    const int t1 = t0 + TPT;

    // prologue: prefetch tiles t0 -> buf0 and t0+1 -> buf1
#pragma unroll
    for (int pp = 0; pp < 2; pp++) {
        int s0 = (t0 + pp) * 64;
        uint32_t srcd = sb + SRC_OFF(pp);
        uint32_t sad  = sb + SA_OFF(pp);
#pragma unroll
        for (int j = 0; j < 8; j++) {
            int idx = tid + j * 128;
            int row = idx >> 4, ch = idx & 15;
            cp16(srcd + row * PITCH + ch * 16, &g_Mb[(size_t)(s0 + row) * D + ch * 8]);
        }
#pragma unroll
        for (int j = 0; j < 2; j++) {
            int idx = tid + j * 128;
            int u = idx >> 4, cc = (idx & 15) * 4;
            if (s0 + cc + 4 <= S)
                cp16(sad + u * PITCH + cc * 4, &A_us[(size_t)sUid[u] * S + s0 + cc]);
        }
        CP_COMMIT();
    }

    // per-thread ldmatrix address components
    const uint32_t sqA0 = sb + SQ_OFF + (32 * w + (lane & 15)) * PITCH + (lane >> 4) * 16;
    const uint32_t b1o = (((lane >> 4) & 1) * 8 + (lane & 7)) * PITCH + ((lane >> 3) & 1) * 16;
    const uint32_t vo  = (((lane >> 3) & 1) * 8 + (lane & 7)) * PITCH + (lane >> 4) * 16;
    const int cb = 2 * (lane & 3);

    float oacc[2][16][4];
#pragma unroll
    for (int mh = 0; mh < 2; mh++)
#pragma unroll
        for (int n = 0; n < 16; n++)
#pragma unroll
            for (int q = 0; q < 4; q++) oacc[mh][n][q] = 0.f;
    float esum[2][2];
    esum[0][0] = esum[0][1] = esum[1][0] = esum[1][1] = 0.f;

    int stage = 0;
    for (int t = t0; t < t1; ++t) {
        if (t + 1 < t1) { CP_WAIT1(); } else { CP_WAIT0(); }   // tile t's group complete
        __syncthreads();
        if (t + 2 < t1) {   // prefetch t+2 into the buffer compute t-1 just released
            int s0n = (t + 2) * 64;
            int st2 = stage + 2; if (st2 >= 3) st2 -= 3;
            uint32_t srcn = sb + SRC_OFF(st2);
            uint32_t san  = sb + SA_OFF(st2);
#pragma unroll
            for (int j = 0; j < 8; j++) {
                int idx = tid + j * 128;
                int row = idx >> 4, ch = idx & 15;
                cp16(srcn + row * PITCH + ch * 16, &g_Mb[(size_t)(s0n + row) * D + ch * 8]);
            }
#pragma unroll
            for (int j = 0; j < 2; j++) {
                int idx = tid + j * 128;
                int u = idx >> 4, cc = (idx & 15) * 4;
                if (s0n + cc + 4 <= S)
                    cp16(san + u * PITCH + cc * 4, &A_us[(size_t)sUid[u] * S + s0n + cc]);
            }
            CP_COMMIT();
        }
        uint32_t srcb = sb + SRC_OFF(stage);
        const float* sAa = (const float*)(sm + SA_OFF(stage));
        // warp w owns users 4w..4w+3: mh0 -> users 4w,4w+1 ; mh1 -> users 4w+2,4w+3
        const float* aP00 = sAa + (4 * w + 0) * 68 + cb;
        const float* aP01 = sAa + (4 * w + 1) * 68 + cb;
        const float* aP10 = sAa + (4 * w + 2) * 68 + cb;
        const float* aP11 = sAa + (4 * w + 3) * 68 + cb;
        int s0 = t * 64;
        if (t == NT64 - 1)
            tile_body<true >(sqA0, srcb, aP00, aP01, aP10, aP11, s0 + cb, oacc, esum, b1o, vo);
        else
            tile_body<false>(sqA0, srcb, aP00, aP01, aP10, aP11, s0 + cb, oacc, esum, b1o, vo);
        if (++stage == 3) stage = 0;
    }

    // ---- denominators: reduce over the 4 lanes sharing each row, RED into g_Den ----
#pragma unroll
    for (int mh = 0; mh < 2; mh++)
#pragma unroll
        for (int hh = 0; hh < 2; hh++) {
            esum[mh][hh] += __shfl_xor_sync(0xffffffffu, esum[mh][hh], 1);
            esum[mh][hh] += __shfl_xor_sync(0xffffffffu, esum[mh][hh], 2);
        }
    int r0 = rowbase + 32 * w + (lane >> 2);
    if ((lane & 3) == 0) {
        atomicAdd(&g_Den[r0],      esum[0][0]);
        atomicAdd(&g_Den[r0 + 8],  esum[0][1]);
        atomicAdd(&g_Den[r0 + 16], esum[1][0]);
        atomicAdd(&g_Den[r0 + 24], esum[1][1]);
    }
    // ---- raw numerators: RED (fire-and-forget) into g_Num ----
#pragma unroll
    for (int mh = 0; mh < 2; mh++) {
        int rr = r0 + 16 * mh;
#pragma unroll
        for (int nf = 0; nf < 16; nf++) {
            int c = 8 * nf + cb;
            float* d0 = &g_Num[(size_t)rr * D + c];
            float* d1 = &g_Num[(size_t)(rr + 8) * D + c];
            atomicAdd(d0,     oacc[mh][nf][0]);
            atomicAdd(d0 + 1, oacc[mh][nf][1]);
            atomicAdd(d1,     oacc[mh][nf][2]);
            atomicAdd(d1 + 1, oacc[mh][nf][3]);
        }
    }
}

// ---------------- Kernel 3: normalize + W1 GEMM (8-way split-K, 1024 thr) + elu + Xu ----------------
__global__ __launch_bounds__(1024)
void out_kernel(const int* __restrict__ uid,
                const float* __restrict__ user_emb,
                const float* __restrict__ W1,
                float* __restrict__ out) {
    extern __shared__ float dynsm[];
    float* smc  = dynsm;            // [8 users][1024]
    float* sred = dynsm + 8 * 1024; // [8 grp][8 users * 128 cols]
    float* sden = sred + 8 * 1024;  // [64] reciprocal denominators
    int bu = blockIdx.x * 8;
    int tid = threadIdx.x;
    if (tid < 64) sden[tid] = 1.f / g_Den[bu * 8 + tid];
    __syncthreads();
    // load + normalize m_hat for 8 users (2048 float4, 1024 threads -> 2 each)
#pragma unroll
    for (int jj = 0; jj < 2; jj++) {
        int ii = tid + jj * 1024;
        float4 v = *(const float4*)&g_Num[(size_t)bu * 1024 + (size_t)ii * 4];
        float inv = sden[ii >> 5];      // row = (ii*4)/128
        v.x *= inv; v.y *= inv; v.z *= inv; v.w *= inv;
        *(float4*)&smc[ii * 4] = v;
    }
    __syncthreads();
    int col = tid & 127;
    int grp = tid >> 7;          // 0..7, covers k in [grp*128, grp*128+128)
    int ibase = grp * 128;
    float acc[8];
#pragma unroll
    for (int uu = 0; uu < 8; uu++) acc[uu] = 0.f;
#pragma unroll 4
    for (int i = 0; i < 128; i++) {
        float wv = W1[(ibase + i) * D + col];     // coalesced across lanes
#pragma unroll
        for (int uu = 0; uu < 8; uu++) acc[uu] += smc[uu * 1024 + ibase + i] * wv;
    }
#pragma unroll
    for (int uu = 0; uu < 8; uu++) sred[grp * 1024 + uu * 128 + col] = acc[uu];
    __syncthreads();
    // one thread per (user, col): combine 8 groups, elu, residual
    int uu = tid >> 7;           // reuse grp slot as user index
    float v = 0.f;
#pragma unroll
    for (int g = 0; g < 8; g++) v += sred[g * 1024 + uu * 128 + col];
    float e = v > 0.f ? v : expm1f(v);
    out[(size_t)(bu + uu) * D + col] = e + user_emb[(size_t)uid[bu + uu] * D + col];
}

// ---------------------------------------------------------------------------
extern "C" void kernel_launch(void* const* d_in, const int* in_sizes, int n_in,
                              void* d_out, int out_size) {
    const int*   X_user_id = (const int*)d_in[0];
    const float* user_emb  = (const float*)d_in[1];
    const float* src       = (const float*)d_in[2];
    const float* Wcm       = (const float*)d_in[3];
    const float* W1        = (const float*)d_in[4];
    const float* A_us      = (const float*)d_in[5];
    float* out = (float*)d_out;

    cudaFuncSetAttribute(attn_kernel, cudaFuncAttributeMaxDynamicSharedMemorySize, SMEM_BYTES);
    cudaFuncSetAttribute(out_kernel, cudaFuncAttributeMaxDynamicSharedMemorySize, 65792);

    prep_kernel<<<NQPROJ + NZNUM + NZDEN + NCONV, 256>>>(X_user_id, user_emb, Wcm, src);
    attn_kernel<<<dim3(KSPLIT, NROWS / 128), 128, SMEM_BYTES>>>(X_user_id, A_us);
    out_kernel<<<B / 8, 1024, 65792>>>(X_user_id, user_emb, W1, out);
}